// round 16
// baseline (speedup 1.0000x reference)
#include <cuda_runtime.h>

// SPConv fused GNN, R16: edge kernel at TE=128 / 71KB smem -> 3 CTAs/SM
// (24 warps), 8ch x 4edge (2+2 split) tiles; zero_kernel merged into pq.

#define TPB 512        // pq/out kernels
#define TPB_E 256      // edge kernel (8 warps)
#define TE 256         // pq/out tile
#define AP 260
#define TE_E 128       // edge tile
#define APE 132

typedef unsigned long long ull;

__device__ float g_cnt[65536];
__device__ int g_idx64;
__device__ float g_P[3276800];   // z @ Wm1[0:64]
__device__ float g_Q[3276800];   // z @ Wm1[64:128]

__device__ __forceinline__ void ffma2(ull& acc, ull a, ull b) {
    asm("fma.rn.f32x2 %0, %1, %2, %0;" : "+l"(acc) : "l"(a), "l"(b));
}
__device__ __forceinline__ ull dup2(float w) {
    ull r;
    asm("mov.b64 %0, {%1, %1};" : "=l"(r) : "r"(__float_as_uint(w)));
    return r;
}
__device__ __forceinline__ ull pack2(float lo, float hi) {
    ull r;
    asm("mov.b64 %0, {%1, %2};" : "=l"(r)
        : "r"(__float_as_uint(lo)), "r"(__float_as_uint(hi)));
    return r;
}
__device__ __forceinline__ void unpack2(ull v, float& lo, float& hi) {
    unsigned a, b;
    asm("mov.b64 {%0, %1}, %2;" : "=r"(a), "=r"(b) : "l"(v));
    lo = __uint_as_float(a);
    hi = __uint_as_float(b);
}
__device__ __forceinline__ void red_add_v4(float* p, float x, float y,
                                           float z, float w) {
    asm volatile("red.global.add.v4.f32 [%0], {%1, %2, %3, %4};"
                 :: "l"(p), "f"(x), "f"(y), "f"(z), "f"(w) : "memory");
}

__global__ void detect_kernel(const unsigned long long* __restrict__ ei) {
    if (threadIdx.x == 0 && blockIdx.x == 0) {
        int is64 = 1;
        for (int i = 0; i < 64; ++i)
            if ((ei[i] >> 32) != 0ull) { is64 = 0; break; }
        g_idx64 = is64;
    }
}

// ======== edge GEMM: 8 channels x 4 edges (2 + 2 from the two halves) ======
__device__ __forceinline__ void gemm84(const float* __restrict__ H,
                                       const float* __restrict__ W, int K,
                                       int cb, int eb0, int eb1,
                                       ull acc[4][4]) {
#pragma unroll 4
    for (int k = 0; k < K; ++k) {
        ulonglong2 wA = *reinterpret_cast<const ulonglong2*>(W + k * 64 + cb);
        ulonglong2 wB = *reinterpret_cast<const ulonglong2*>(W + k * 64 + cb + 4);
        ull w2[4] = {wA.x, wA.y, wB.x, wB.y};
        const float* hr = H + k * APE;
        float2 ha = *reinterpret_cast<const float2*>(hr + eb0);
        float2 hb = *reinterpret_cast<const float2*>(hr + eb1);
        ull h2[4] = {dup2(ha.x), dup2(ha.y), dup2(hb.x), dup2(hb.y)};
#pragma unroll
        for (int cp = 0; cp < 4; ++cp)
#pragma unroll
            for (int e = 0; e < 4; ++e)
                ffma2(acc[cp][e], w2[cp], h2[e]);
    }
}

__device__ __forceinline__ void zero84(ull acc[4][4]) {
#pragma unroll
    for (int cp = 0; cp < 4; ++cp)
#pragma unroll
        for (int e = 0; e < 4; ++e) acc[cp][e] = 0ull;
}

// relu(acc + bias) -> D[ch][edges], float2 stores at both half-bases
__device__ __forceinline__ void store_relu84(float* __restrict__ D,
                                             ull acc[4][4],
                                             const float* __restrict__ bias,
                                             int cb, int eb0, int eb1) {
#pragma unroll
    for (int cp = 0; cp < 4; ++cp) {
        float lo[4], hi[4];
#pragma unroll
        for (int e = 0; e < 4; ++e) unpack2(acc[cp][e], lo[e], hi[e]);
        float b0 = bias[cb + 2 * cp], b1 = bias[cb + 2 * cp + 1];
        float* r0 = D + (cb + 2 * cp) * APE;
        float* r1 = D + (cb + 2 * cp + 1) * APE;
        *reinterpret_cast<float2*>(r0 + eb0) =
            make_float2(fmaxf(lo[0] + b0, 0.0f), fmaxf(lo[1] + b0, 0.0f));
        *reinterpret_cast<float2*>(r0 + eb1) =
            make_float2(fmaxf(lo[2] + b0, 0.0f), fmaxf(lo[3] + b0, 0.0f));
        *reinterpret_cast<float2*>(r1 + eb0) =
            make_float2(fmaxf(hi[0] + b1, 0.0f), fmaxf(hi[1] + b1, 0.0f));
        *reinterpret_cast<float2*>(r1 + eb1) =
            make_float2(fmaxf(hi[2] + b1, 0.0f), fmaxf(hi[3] + b1, 0.0f));
    }
}

// ======== 8ch x 4edge GEMM (pq/out kernels, proven) ========
__device__ __forceinline__ void gemmp(const float* __restrict__ H, int hp,
                                      const float* __restrict__ W, int K,
                                      int cb, int eb, ull acc[4][4]) {
#pragma unroll 4
    for (int k = 0; k < K; ++k) {
        ulonglong2 wA = *reinterpret_cast<const ulonglong2*>(W + k * 64 + cb);
        ulonglong2 wB = *reinterpret_cast<const ulonglong2*>(W + k * 64 + cb + 4);
        ull w2[4] = {wA.x, wA.y, wB.x, wB.y};
        float4 h = *reinterpret_cast<const float4*>(H + k * hp + eb);
        ull h2[4] = {dup2(h.x), dup2(h.y), dup2(h.z), dup2(h.w)};
#pragma unroll
        for (int cp = 0; cp < 4; ++cp)
#pragma unroll
            for (int e = 0; e < 4; ++e)
                ffma2(acc[cp][e], w2[cp], h2[e]);
    }
}

__device__ __forceinline__ void zero_acc(ull acc[4][4]) {
#pragma unroll
    for (int cp = 0; cp < 4; ++cp)
#pragma unroll
        for (int e = 0; e < 4; ++e) acc[cp][e] = 0ull;
}

// ---- pq_kernel: P = z @ Wm1[0:64], Q = z @ Wm1[64:128]; zeroes S1 + cnt ----
// smem: sW 8192 | sZ 64*AP=16640  -> 24832 floats
__global__ __launch_bounds__(TPB) void pq_kernel(
    const float* __restrict__ z, const float* __restrict__ Wm1,
    float* __restrict__ S1, int N, int ntiles) {
    extern __shared__ float sm[];
    float* sW = sm;
    float* sZ = sm + 8192;
    const int tid = threadIdx.x;
    for (int i = tid; i < 8192; i += TPB) sW[i] = Wm1[i];
    __syncthreads();

    const int wid = tid >> 5, lane = tid & 31;
    const int grp = wid >> 3;
    const int cb = (wid & 7) * 8;
    const int eb = grp * 128 + lane * 4;

    for (int tile = blockIdx.x; tile < ntiles; tile += gridDim.x) {
        const int base = tile * TE;
        for (int i = tid; i < 64 * TE; i += TPB) {
            int nl = i >> 6, k = i & 63;
            int gn = base + nl;
            float zv = 0.0f;
            if (gn < N) {
                zv = z[(size_t)gn * 64 + k];
                S1[(size_t)gn * 64 + k] = 0.0f;       // zero sums buffer
            }
            sZ[k * AP + nl] = zv;
        }
        if (tid < TE) {
            int gn = base + tid;
            if (gn < N) g_cnt[gn] = 0.0f;
        }
        __syncthreads();

        ull acc[4][4];
#pragma unroll
        for (int pass = 0; pass < 2; ++pass) {
            zero_acc(acc);
            gemmp(sZ, AP, sW + pass * 64 * 64, 64, cb, eb, acc);
            float* dst = pass == 0 ? g_P : g_Q;
#pragma unroll
            for (int e = 0; e < 4; ++e) {
                int gn = base + eb + e;
                if (gn < N) {
                    float v[8];
#pragma unroll
                    for (int cp = 0; cp < 4; ++cp)
                        unpack2(acc[cp][e], v[2 * cp], v[2 * cp + 1]);
                    *reinterpret_cast<float4*>(&dst[(size_t)gn * 64 + cb]) =
                        make_float4(v[0], v[1], v[2], v[3]);
                    *reinterpret_cast<float4*>(&dst[(size_t)gn * 64 + cb + 4]) =
                        make_float4(v[4], v[5], v[6], v[7]);
                }
            }
        }
        __syncthreads();
    }
}

// ======== edge_kernel (TPB_E=256, TE_E=128, 3 CTAs/SM) ========
// smem floats:
//      0 : sWe2  4096
//   4096 : sWm1c 4096  (Wm1 rows 128..191)
//   8192 : sWe1   192
//   8384 : be1 64 | 8448 : be2 64 | 8512 : bm1 64
//   8576 : sDelta 3*APE = 396
//   8972 : sBuf 64*APE = 8448
//  17420 : src/dst (2*TE_E ints = 256 floats)
// total 17676 floats = 70,704 B -> 3 CTAs/SM
__global__ __launch_bounds__(TPB_E, 3) void edge_kernel(
    const float* __restrict__ cent, const void* __restrict__ ei_raw,
    const float* __restrict__ We1, const float* __restrict__ be1,
    const float* __restrict__ We2, const float* __restrict__ be2,
    const float* __restrict__ Wm1, const float* __restrict__ bm1,
    float* __restrict__ S1, int E, int N, int ntiles) {
    extern __shared__ float sm[];
    float* sWe2 = sm;
    float* sWm1c = sm + 4096;
    float* sWe1 = sm + 8192;
    float* sbe1 = sm + 8384;
    float* sbe2 = sm + 8448;
    float* sbm1 = sm + 8512;
    float* sDelta = sm + 8576;
    float* sBuf = sm + 8972;
    int* sSrc = (int*)(sm + 17420);
    int* sDst = sSrc + TE_E;

    const int tid = threadIdx.x;
    const int idx64 = g_idx64;
    const long long* ei64 = (const long long*)ei_raw;
    const int* ei32 = (const int*)ei_raw;

    for (int i = tid; i < 4096; i += TPB_E) {
        sWe2[i] = We2[i];
        sWm1c[i] = Wm1[128 * 64 + i];
    }
    if (tid < 192) sWe1[tid] = We1[tid];
    if (tid < 64) {
        sbe1[tid] = be1[tid]; sbe2[tid] = be2[tid]; sbm1[tid] = bm1[tid];
    }
    __syncthreads();

    const int wid = tid >> 5, lane = tid & 31;
    const int cb = wid * 8;           // 8 warps x 8 channels = 64
    const int eb0 = lane * 2;         // edges 0..63 (2 per lane)
    const int eb1 = 64 + lane * 2;    // edges 64..127 (2 per lane)

    for (int tile = blockIdx.x; tile < ntiles; tile += gridDim.x) {
        const int base = tile * TE_E;

        if (tid < TE_E) {
            int e = base + tid;
            int s = 0, d = -1;
            if (e < E) {
                if (idx64) { s = (int)ei64[e]; d = (int)ei64[(size_t)E + e]; }
                else       { s = ei32[e];      d = ei32[E + e]; }
                if (s < 0 || s >= N) s = 0;
                if (d < 0 || d >= N) d = 0;
            }
            sSrc[tid] = s;
            sDst[tid] = d;
        }
        __syncthreads();

        // delta = centroids[dst] - centroids[src]
        for (int i = tid; i < 3 * TE_E; i += TPB_E) {
            int e = i & (TE_E - 1), comp = i >> 7;
            int s = sSrc[e], d = sDst[e];
            int dd = (d < 0) ? s : d;
            sDelta[comp * APE + e] =
                cent[(size_t)dd * 3 + comp] - cent[(size_t)s * 3 + comp];
        }
        __syncthreads();

        ull acc[4][4];

        // L1: e1 = relu(delta @ We1 + be1) -> sBuf
        zero84(acc);
        gemm84(sDelta, sWe1, 3, cb, eb0, eb1, acc);
        store_relu84(sBuf, acc, sbe1, cb, eb0, eb1);
        __syncthreads();

        // L2: e = relu(e1 @ We2 + be2); reuse sBuf (read -> bar -> write)
        zero84(acc);
        gemm84(sBuf, sWe2, 64, cb, eb0, eb1, acc);
        __syncthreads();                 // all reads of e1 complete
        store_relu84(sBuf, acc, sbe2, cb, eb0, eb1);
        __syncthreads();

        // L3: m1 = relu(e @ Wm1c + P[src] + Q[dst] + bm1) -> scatter S1[dst]
        zero84(acc);
        gemm84(sBuf, sWm1c, 64, cb, eb0, eb1, acc);
#pragma unroll
        for (int e = 0; e < 4; ++e) {
            int ed = (e < 2) ? (eb0 + e) : (eb1 + e - 2);
            int d = sDst[ed];
            if (d >= 0) {
                int s = sSrc[ed];
                float4 p0 = *reinterpret_cast<const float4*>(&g_P[(size_t)s * 64 + cb]);
                float4 p1 = *reinterpret_cast<const float4*>(&g_P[(size_t)s * 64 + cb + 4]);
                float4 q0 = *reinterpret_cast<const float4*>(&g_Q[(size_t)d * 64 + cb]);
                float4 q1 = *reinterpret_cast<const float4*>(&g_Q[(size_t)d * 64 + cb + 4]);
                float v[8];
#pragma unroll
                for (int cp = 0; cp < 4; ++cp)
                    unpack2(acc[cp][e], v[2 * cp], v[2 * cp + 1]);
                v[0] = fmaxf(v[0] + p0.x + q0.x + sbm1[cb + 0], 0.0f);
                v[1] = fmaxf(v[1] + p0.y + q0.y + sbm1[cb + 1], 0.0f);
                v[2] = fmaxf(v[2] + p0.z + q0.z + sbm1[cb + 2], 0.0f);
                v[3] = fmaxf(v[3] + p0.w + q0.w + sbm1[cb + 3], 0.0f);
                v[4] = fmaxf(v[4] + p1.x + q1.x + sbm1[cb + 4], 0.0f);
                v[5] = fmaxf(v[5] + p1.y + q1.y + sbm1[cb + 5], 0.0f);
                v[6] = fmaxf(v[6] + p1.z + q1.z + sbm1[cb + 6], 0.0f);
                v[7] = fmaxf(v[7] + p1.w + q1.w + sbm1[cb + 7], 0.0f);
                float* p = &S1[(size_t)d * 64 + cb];
                red_add_v4(p, v[0], v[1], v[2], v[3]);
                red_add_v4(p + 4, v[4], v[5], v[6], v[7]);
            }
        }
        if (tid < TE_E && sDst[tid] >= 0) atomicAdd(&g_cnt[sDst[tid]], 1.0f);
        __syncthreads();
    }
}

// ---- out_kernel ----
// M = (S1 @ Wm2 + cnt*bm2) / max(cnt,1);  out = relu([z, M] @ Wu1 + bu1)
// smem floats: 0: sWu1 8192 | 8192: sWm2 4096 | 12288: bu1 64 | 12352: bm2 64
//              12416: sZM 128*AP = 33280   -> 45696 floats
__global__ __launch_bounds__(TPB) void out_kernel(
    const float* __restrict__ z, const float* __restrict__ S1,
    const float* __restrict__ Wu1, const float* __restrict__ bu1,
    const float* __restrict__ Wm2, const float* __restrict__ bm2,
    float* __restrict__ out, int N, int ntiles) {
    extern __shared__ float sm[];
    float* sWu1 = sm;
    float* sWm2 = sm + 8192;
    float* sbu1 = sm + 12288;
    float* sbm2 = sm + 12352;
    float* sZM = sm + 12416;

    const int tid = threadIdx.x;
    for (int i = tid; i < 8192; i += TPB) sWu1[i] = Wu1[i];
    for (int i = tid; i < 4096; i += TPB) sWm2[i] = Wm2[i];
    if (tid < 64) { sbu1[tid] = bu1[tid]; sbm2[tid] = bm2[tid]; }
    __syncthreads();

    const int wid = tid >> 5, lane = tid & 31;
    const int grp = wid >> 3;
    const int cb = (wid & 7) * 8;
    const int eb = grp * 128 + lane * 4;

    for (int tile = blockIdx.x; tile < ntiles; tile += gridDim.x) {
        const int base = tile * TE;
        for (int i = tid; i < 64 * TE; i += TPB) {
            int nl = i >> 6, k = i & 63;
            int gn = base + nl;
            float zv = 0.0f, sv = 0.0f;
            if (gn < N) {
                zv = z[(size_t)gn * 64 + k];
                sv = S1[(size_t)gn * 64 + k];
            }
            sZM[k * AP + nl] = zv;
            sZM[(64 + k) * AP + nl] = sv;
        }
        __syncthreads();

        // stage 1: Mpre = S1tile @ Wm2
        ull acc[4][4];
        zero_acc(acc);
        gemmp(sZM + 64 * AP, AP, sWm2, 64, cb, eb, acc);

        float Mv[4][8];
#pragma unroll
        for (int e = 0; e < 4; ++e) {
            int gn = base + eb + e;
            float c = (gn < N) ? g_cnt[gn] : 0.0f;
            float rinv = 1.0f / fmaxf(c, 1.0f);
#pragma unroll
            for (int cp = 0; cp < 4; ++cp) {
                float lo, hi;
                unpack2(acc[cp][e], lo, hi);
                Mv[e][2 * cp] = (lo + c * sbm2[cb + 2 * cp]) * rinv;
                Mv[e][2 * cp + 1] = (hi + c * sbm2[cb + 2 * cp + 1]) * rinv;
            }
        }
        __syncthreads();

#pragma unroll
        for (int cp = 0; cp < 4; ++cp) {
            float4 v0 = make_float4(Mv[0][2 * cp], Mv[1][2 * cp],
                                    Mv[2][2 * cp], Mv[3][2 * cp]);
            float4 v1 = make_float4(Mv[0][2 * cp + 1], Mv[1][2 * cp + 1],
                                    Mv[2][2 * cp + 1], Mv[3][2 * cp + 1]);
            *reinterpret_cast<float4*>(sZM + (64 + cb + 2 * cp) * AP + eb) = v0;
            *reinterpret_cast<float4*>(sZM + (64 + cb + 2 * cp + 1) * AP + eb) = v1;
        }
        __syncthreads();

        // stage 2: out = relu([z, M] @ Wu1 + bu1)
        zero_acc(acc);
        gemmp(sZM, AP, sWu1, 128, cb, eb, acc);
#pragma unroll
        for (int e = 0; e < 4; ++e) {
            int gn = base + eb + e;
            if (gn < N) {
                float v[8];
#pragma unroll
                for (int cp = 0; cp < 4; ++cp)
                    unpack2(acc[cp][e], v[2 * cp], v[2 * cp + 1]);
                float4 o0, o1;
                o0.x = fmaxf(v[0] + sbu1[cb + 0], 0.0f);
                o0.y = fmaxf(v[1] + sbu1[cb + 1], 0.0f);
                o0.z = fmaxf(v[2] + sbu1[cb + 2], 0.0f);
                o0.w = fmaxf(v[3] + sbu1[cb + 3], 0.0f);
                o1.x = fmaxf(v[4] + sbu1[cb + 4], 0.0f);
                o1.y = fmaxf(v[5] + sbu1[cb + 5], 0.0f);
                o1.z = fmaxf(v[6] + sbu1[cb + 6], 0.0f);
                o1.w = fmaxf(v[7] + sbu1[cb + 7], 0.0f);
                *reinterpret_cast<float4*>(&out[(size_t)gn * 64 + cb]) = o0;
                *reinterpret_cast<float4*>(&out[(size_t)gn * 64 + cb + 4]) = o1;
            }
        }
        __syncthreads();
    }
}

extern "C" void kernel_launch(void* const* d_in, const int* in_sizes, int n_in,
                              void* d_out, int out_size) {
    const float* z    = (const float*)d_in[0];
    const float* cent = (const float*)d_in[1];
    const void* ei    = d_in[2];
    const float* We1 = (const float*)d_in[3];
    const float* be1 = (const float*)d_in[4];
    const float* We2 = (const float*)d_in[5];
    const float* be2 = (const float*)d_in[6];
    const float* Wm1 = (const float*)d_in[7];
    const float* bm1 = (const float*)d_in[8];
    const float* Wm2 = (const float*)d_in[9];
    const float* bm2 = (const float*)d_in[10];
    const float* Wu1 = (const float*)d_in[11];
    const float* bu1 = (const float*)d_in[12];
    float* out = (float*)d_out;

    const int N = in_sizes[0] / 64;
    const int E = in_sizes[2] / 2;
    const int ntiles_e = (E + TE_E - 1) / TE_E;
    const int ntiles_n = (N + TE - 1) / TE;

    const size_t smem_edge = 17676 * sizeof(float);
    const size_t smem_pq   = 24832 * sizeof(float);
    const size_t smem_out  = 45696 * sizeof(float);

    cudaFuncSetAttribute(edge_kernel, cudaFuncAttributeMaxDynamicSharedMemorySize,
                         (int)smem_edge);
    cudaFuncSetAttribute(pq_kernel, cudaFuncAttributeMaxDynamicSharedMemorySize,
                         (int)smem_pq);
    cudaFuncSetAttribute(out_kernel, cudaFuncAttributeMaxDynamicSharedMemorySize,
                         (int)smem_out);

    detect_kernel<<<1, 32>>>((const unsigned long long*)ei);
    pq_kernel<<<ntiles_n, TPB, smem_pq>>>(z, Wm1, out, N, ntiles_n);
    edge_kernel<<<444, TPB_E, smem_edge>>>(cent, ei,
                                           We1, be1, We2, be2,
                                           Wm1, bm1,
                                           out, E, N, ntiles_e);
    out_kernel<<<ntiles_n, TPB, smem_out>>>(z, out, Wu1, bu1, Wm2, bm2,
                                            out, N, ntiles_n);
}

// round 17
// speedup vs baseline: 2.3403x; 2.3403x over previous
#include <cuda_runtime.h>

// SPConv fused GNN, R17: edge GEMMs on tf32 mma.sync (m16n8k8), edge-major
// smem staging, weights transposed; pq/out kernels stay fp32 FFMA2 (proven).

#define TPB 512        // pq/out kernels
#define TPB_E 256      // edge kernel (8 warps)
#define TE 256         // pq/out tile
#define AP 260
#define TE_E 128       // edge tile (rows of H)
#define KP 68          // H pitch: (4*row + tig) mod 32 conflict-free

typedef unsigned long long ull;
typedef unsigned int uint;

__device__ float g_cnt[65536];
__device__ int g_idx64;
__device__ float g_P[3276800];   // z @ Wm1[0:64]
__device__ float g_Q[3276800];   // z @ Wm1[64:128]

__device__ __forceinline__ void ffma2(ull& acc, ull a, ull b) {
    asm("fma.rn.f32x2 %0, %1, %2, %0;" : "+l"(acc) : "l"(a), "l"(b));
}
__device__ __forceinline__ ull dup2(float w) {
    ull r;
    asm("mov.b64 %0, {%1, %1};" : "=l"(r) : "r"(__float_as_uint(w)));
    return r;
}
__device__ __forceinline__ void unpack2(ull v, float& lo, float& hi) {
    unsigned a, b;
    asm("mov.b64 {%0, %1}, %2;" : "=r"(a), "=r"(b) : "l"(v));
    lo = __uint_as_float(a);
    hi = __uint_as_float(b);
}
__device__ __forceinline__ void red_add_v4(float* p, float x, float y,
                                           float z, float w) {
    asm volatile("red.global.add.v4.f32 [%0], {%1, %2, %3, %4};"
                 :: "l"(p), "f"(x), "f"(y), "f"(z), "f"(w) : "memory");
}
__device__ __forceinline__ uint cvt_tf32(float x) {
    uint r;
    asm("cvt.rna.tf32.f32 %0, %1;" : "=r"(r) : "f"(x));
    return r;
}
__device__ __forceinline__ void mma_tf32(float d[4], uint a0, uint a1,
                                         uint a2, uint a3, uint b0, uint b1) {
    asm volatile(
        "mma.sync.aligned.m16n8k8.row.col.f32.tf32.tf32.f32 "
        "{%0,%1,%2,%3}, {%4,%5,%6,%7}, {%8,%9}, {%0,%1,%2,%3};"
        : "+f"(d[0]), "+f"(d[1]), "+f"(d[2]), "+f"(d[3])
        : "r"(a0), "r"(a1), "r"(a2), "r"(a3), "r"(b0), "r"(b1));
}

__global__ void detect_kernel(const unsigned long long* __restrict__ ei) {
    if (threadIdx.x == 0 && blockIdx.x == 0) {
        int is64 = 1;
        for (int i = 0; i < 64; ++i)
            if ((ei[i] >> 32) != 0ull) { is64 = 0; break; }
        g_idx64 = is64;
    }
}

// ======== fp32 8ch x 4edge GEMM (pq/out kernels, proven) ========
__device__ __forceinline__ void gemmp(const float* __restrict__ H, int hp,
                                      const float* __restrict__ W, int K,
                                      int cb, int eb, ull acc[4][4]) {
#pragma unroll 4
    for (int k = 0; k < K; ++k) {
        ulonglong2 wA = *reinterpret_cast<const ulonglong2*>(W + k * 64 + cb);
        ulonglong2 wB = *reinterpret_cast<const ulonglong2*>(W + k * 64 + cb + 4);
        ull w2[4] = {wA.x, wA.y, wB.x, wB.y};
        float4 h = *reinterpret_cast<const float4*>(H + k * hp + eb);
        ull h2[4] = {dup2(h.x), dup2(h.y), dup2(h.z), dup2(h.w)};
#pragma unroll
        for (int cp = 0; cp < 4; ++cp)
#pragma unroll
            for (int e = 0; e < 4; ++e)
                ffma2(acc[cp][e], w2[cp], h2[e]);
    }
}

__device__ __forceinline__ void zero_acc(ull acc[4][4]) {
#pragma unroll
    for (int cp = 0; cp < 4; ++cp)
#pragma unroll
        for (int e = 0; e < 4; ++e) acc[cp][e] = 0ull;
}

// ---- pq_kernel: P = z @ Wm1[0:64], Q = z @ Wm1[64:128]; zeroes S1 + cnt ----
__global__ __launch_bounds__(TPB) void pq_kernel(
    const float* __restrict__ z, const float* __restrict__ Wm1,
    float* __restrict__ S1, int N, int ntiles) {
    extern __shared__ float sm[];
    float* sW = sm;
    float* sZ = sm + 8192;
    const int tid = threadIdx.x;
    for (int i = tid; i < 8192; i += TPB) sW[i] = Wm1[i];
    __syncthreads();

    const int wid = tid >> 5, lane = tid & 31;
    const int grp = wid >> 3;
    const int cb = (wid & 7) * 8;
    const int eb = grp * 128 + lane * 4;

    for (int tile = blockIdx.x; tile < ntiles; tile += gridDim.x) {
        const int base = tile * TE;
        for (int i = tid; i < 64 * TE; i += TPB) {
            int nl = i >> 6, k = i & 63;
            int gn = base + nl;
            float zv = 0.0f;
            if (gn < N) {
                zv = z[(size_t)gn * 64 + k];
                S1[(size_t)gn * 64 + k] = 0.0f;
            }
            sZ[k * AP + nl] = zv;
        }
        if (tid < TE) {
            int gn = base + tid;
            if (gn < N) g_cnt[gn] = 0.0f;
        }
        __syncthreads();

        ull acc[4][4];
#pragma unroll
        for (int pass = 0; pass < 2; ++pass) {
            zero_acc(acc);
            gemmp(sZ, AP, sW + pass * 64 * 64, 64, cb, eb, acc);
            float* dst = pass == 0 ? g_P : g_Q;
#pragma unroll
            for (int e = 0; e < 4; ++e) {
                int gn = base + eb + e;
                if (gn < N) {
                    float v[8];
#pragma unroll
                    for (int cp = 0; cp < 4; ++cp)
                        unpack2(acc[cp][e], v[2 * cp], v[2 * cp + 1]);
                    *reinterpret_cast<float4*>(&dst[(size_t)gn * 64 + cb]) =
                        make_float4(v[0], v[1], v[2], v[3]);
                    *reinterpret_cast<float4*>(&dst[(size_t)gn * 64 + cb + 4]) =
                        make_float4(v[4], v[5], v[6], v[7]);
                }
            }
        }
        __syncthreads();
    }
}

// ======== edge_kernel (tf32 mma, TPB_E=256, TE_E=128, 3 CTAs/SM) ========
// smem floats:
//      0 : sWe2t  [64c][KP] = 4352   (We2 transposed, tf32)
//   4352 : sWm1ct [64c][KP] = 4352   (Wm1 rows 128..191 transposed, tf32)
//   8704 : sWe1t  [64c][12] =  768   (We1 transposed, k padded to 8, tf32)
//   9472 : be1 64 | 9536: be2 64 | 9600: bm1 64
//   9664 : sH [128e][KP] = 8704      (delta -> e1 -> e -> m1pre)
//  18368 : src/dst (2*128 ints = 256)
// total 18624 floats = 74,496 B -> 3 CTAs/SM
__global__ __launch_bounds__(TPB_E, 3) void edge_kernel(
    const float* __restrict__ cent, const void* __restrict__ ei_raw,
    const float* __restrict__ We1, const float* __restrict__ be1,
    const float* __restrict__ We2, const float* __restrict__ be2,
    const float* __restrict__ Wm1, const float* __restrict__ bm1,
    float* __restrict__ S1, int E, int N, int ntiles) {
    extern __shared__ float sm[];
    float* sWe2t = sm;
    float* sWm1ct = sm + 4352;
    float* sWe1t = sm + 8704;
    float* sbe1 = sm + 9472;
    float* sbe2 = sm + 9536;
    float* sbm1 = sm + 9600;
    float* sH = sm + 9664;
    int* sSrc = (int*)(sm + 18368);
    int* sDst = sSrc + TE_E;

    const int tid = threadIdx.x;
    const int idx64 = g_idx64;
    const long long* ei64 = (const long long*)ei_raw;
    const int* ei32 = (const int*)ei_raw;

    // Stage transposed tf32 weights
    for (int i = tid; i < 4096; i += TPB_E) {
        int c = i >> 6, k = i & 63;
        sWe2t[c * KP + k] = __uint_as_float(cvt_tf32(We2[k * 64 + c]));
        sWm1ct[c * KP + k] = __uint_as_float(cvt_tf32(Wm1[(128 + k) * 64 + c]));
    }
    for (int i = tid; i < 768; i += TPB_E) {
        int c = i / 12, k = i % 12;
        float v = (k < 3) ? We1[k * 64 + c] : 0.0f;
        sWe1t[i] = __uint_as_float(cvt_tf32(v));
    }
    if (tid < 64) {
        sbe1[tid] = be1[tid]; sbe2[tid] = be2[tid]; sbm1[tid] = bm1[tid];
    }
    __syncthreads();

    const int wid = tid >> 5, lane = tid & 31;
    const int g8 = lane >> 2;          // groupID 0..7
    const int tig = lane & 3;          // thread-in-group 0..3
    const int cb = wid * 8;            // this warp's 8-channel N block

    for (int tile = blockIdx.x; tile < ntiles; tile += gridDim.x) {
        const int base = tile * TE_E;

        if (tid < TE_E) {
            int e = base + tid;
            int s = 0, d = -1;
            if (e < E) {
                if (idx64) { s = (int)ei64[e]; d = (int)ei64[(size_t)E + e]; }
                else       { s = ei32[e];      d = ei32[E + e]; }
                if (s < 0 || s >= N) s = 0;
                if (d < 0 || d >= N) d = 0;
            }
            sSrc[tid] = s;
            sDst[tid] = d;
        }
        __syncthreads();

        // Stage delta edge-major into sH cols 0..7 (cols 3..7 zero), tf32
        for (int i = tid; i < TE_E * 8; i += TPB_E) {
            int e = i >> 3, c = i & 7;
            float v = 0.0f;
            if (c < 3) {
                int s = sSrc[e], d = sDst[e];
                int dd = (d < 0) ? s : d;
                v = cent[(size_t)dd * 3 + c] - cent[(size_t)s * 3 + c];
            }
            sH[e * KP + c] = __uint_as_float(cvt_tf32(v));
        }
        __syncthreads();

        float acc[8][4];
        const float bb0_1 = sbe1[cb + 2 * tig], bb1_1 = sbe1[cb + 2 * tig + 1];
        const float bb0_2 = sbe2[cb + 2 * tig], bb1_2 = sbe2[cb + 2 * tig + 1];

        // ---- L1: e1 = relu(delta @ We1 + be1), K=8 (3 valid) ----
#pragma unroll
        for (int mb = 0; mb < 8; ++mb)
#pragma unroll
            for (int i = 0; i < 4; ++i) acc[mb][i] = 0.0f;
        {
            uint b0 = __float_as_uint(sWe1t[(cb + g8) * 12 + tig]);
            uint b1 = __float_as_uint(sWe1t[(cb + g8) * 12 + tig + 4]);
#pragma unroll
            for (int mb = 0; mb < 8; ++mb) {
                int r0 = mb * 16 + g8;
                uint a0 = __float_as_uint(sH[r0 * KP + tig]);
                uint a1 = __float_as_uint(sH[(r0 + 8) * KP + tig]);
                uint a2 = __float_as_uint(sH[r0 * KP + tig + 4]);
                uint a3 = __float_as_uint(sH[(r0 + 8) * KP + tig + 4]);
                mma_tf32(acc[mb], a0, a1, a2, a3, b0, b1);
            }
        }
        __syncthreads();   // all A reads done before overwrite
#pragma unroll
        for (int mb = 0; mb < 8; ++mb) {
            int r0 = mb * 16 + g8;
            uint2 v0, v1;
            v0.x = cvt_tf32(fmaxf(acc[mb][0] + bb0_1, 0.0f));
            v0.y = cvt_tf32(fmaxf(acc[mb][1] + bb1_1, 0.0f));
            v1.x = cvt_tf32(fmaxf(acc[mb][2] + bb0_1, 0.0f));
            v1.y = cvt_tf32(fmaxf(acc[mb][3] + bb1_1, 0.0f));
            *reinterpret_cast<uint2*>(&sH[r0 * KP + cb + 2 * tig]) = v0;
            *reinterpret_cast<uint2*>(&sH[(r0 + 8) * KP + cb + 2 * tig]) = v1;
        }
        __syncthreads();

        // ---- L2: e = relu(e1 @ We2 + be2), K=64 ----
#pragma unroll
        for (int mb = 0; mb < 8; ++mb)
#pragma unroll
            for (int i = 0; i < 4; ++i) acc[mb][i] = 0.0f;
#pragma unroll
        for (int kb = 0; kb < 8; ++kb) {
            int kk = kb * 8;
            uint b0 = __float_as_uint(sWe2t[(cb + g8) * KP + kk + tig]);
            uint b1 = __float_as_uint(sWe2t[(cb + g8) * KP + kk + tig + 4]);
#pragma unroll
            for (int mb = 0; mb < 8; ++mb) {
                int r0 = mb * 16 + g8;
                uint a0 = __float_as_uint(sH[r0 * KP + kk + tig]);
                uint a1 = __float_as_uint(sH[(r0 + 8) * KP + kk + tig]);
                uint a2 = __float_as_uint(sH[r0 * KP + kk + tig + 4]);
                uint a3 = __float_as_uint(sH[(r0 + 8) * KP + kk + tig + 4]);
                mma_tf32(acc[mb], a0, a1, a2, a3, b0, b1);
            }
        }
        __syncthreads();
#pragma unroll
        for (int mb = 0; mb < 8; ++mb) {
            int r0 = mb * 16 + g8;
            uint2 v0, v1;
            v0.x = cvt_tf32(fmaxf(acc[mb][0] + bb0_2, 0.0f));
            v0.y = cvt_tf32(fmaxf(acc[mb][1] + bb1_2, 0.0f));
            v1.x = cvt_tf32(fmaxf(acc[mb][2] + bb0_2, 0.0f));
            v1.y = cvt_tf32(fmaxf(acc[mb][3] + bb1_2, 0.0f));
            *reinterpret_cast<uint2*>(&sH[r0 * KP + cb + 2 * tig]) = v0;
            *reinterpret_cast<uint2*>(&sH[(r0 + 8) * KP + cb + 2 * tig]) = v1;
        }
        __syncthreads();

        // ---- L3: m1pre = e @ Wm1c (raw; PQ + bias + relu in scatter) ----
#pragma unroll
        for (int mb = 0; mb < 8; ++mb)
#pragma unroll
            for (int i = 0; i < 4; ++i) acc[mb][i] = 0.0f;
#pragma unroll
        for (int kb = 0; kb < 8; ++kb) {
            int kk = kb * 8;
            uint b0 = __float_as_uint(sWm1ct[(cb + g8) * KP + kk + tig]);
            uint b1 = __float_as_uint(sWm1ct[(cb + g8) * KP + kk + tig + 4]);
#pragma unroll
            for (int mb = 0; mb < 8; ++mb) {
                int r0 = mb * 16 + g8;
                uint a0 = __float_as_uint(sH[r0 * KP + kk + tig]);
                uint a1 = __float_as_uint(sH[(r0 + 8) * KP + kk + tig]);
                uint a2 = __float_as_uint(sH[r0 * KP + kk + tig + 4]);
                uint a3 = __float_as_uint(sH[(r0 + 8) * KP + kk + tig + 4]);
                mma_tf32(acc[mb], a0, a1, a2, a3, b0, b1);
            }
        }
        __syncthreads();
#pragma unroll
        for (int mb = 0; mb < 8; ++mb) {
            int r0 = mb * 16 + g8;
            *reinterpret_cast<float2*>(&sH[r0 * KP + cb + 2 * tig]) =
                make_float2(acc[mb][0], acc[mb][1]);
            *reinterpret_cast<float2*>(&sH[(r0 + 8) * KP + cb + 2 * tig]) =
                make_float2(acc[mb][2], acc[mb][3]);
        }
        __syncthreads();

        // ---- scatter: m1 = relu(m1pre + P[s] + Q[d] + bm1) -> red.v4 ----
#pragma unroll
        for (int p = 0; p < 4; ++p) {
            int el = p * 32 + (tid >> 3);
            int cb2 = (tid & 7) * 8;
            int d = sDst[el];
            if (d >= 0) {
                int s = sSrc[el];
                float4 m0 = *reinterpret_cast<const float4*>(&sH[el * KP + cb2]);
                float4 m1 = *reinterpret_cast<const float4*>(&sH[el * KP + cb2 + 4]);
                float4 p0 = *reinterpret_cast<const float4*>(&g_P[(size_t)s * 64 + cb2]);
                float4 p1 = *reinterpret_cast<const float4*>(&g_P[(size_t)s * 64 + cb2 + 4]);
                float4 q0 = *reinterpret_cast<const float4*>(&g_Q[(size_t)d * 64 + cb2]);
                float4 q1 = *reinterpret_cast<const float4*>(&g_Q[(size_t)d * 64 + cb2 + 4]);
                float v0 = fmaxf(m0.x + p0.x + q0.x + sbm1[cb2 + 0], 0.0f);
                float v1 = fmaxf(m0.y + p0.y + q0.y + sbm1[cb2 + 1], 0.0f);
                float v2 = fmaxf(m0.z + p0.z + q0.z + sbm1[cb2 + 2], 0.0f);
                float v3 = fmaxf(m0.w + p0.w + q0.w + sbm1[cb2 + 3], 0.0f);
                float v4 = fmaxf(m1.x + p1.x + q1.x + sbm1[cb2 + 4], 0.0f);
                float v5 = fmaxf(m1.y + p1.y + q1.y + sbm1[cb2 + 5], 0.0f);
                float v6 = fmaxf(m1.z + p1.z + q1.z + sbm1[cb2 + 6], 0.0f);
                float v7 = fmaxf(m1.w + p1.w + q1.w + sbm1[cb2 + 7], 0.0f);
                float* pp = &S1[(size_t)d * 64 + cb2];
                red_add_v4(pp, v0, v1, v2, v3);
                red_add_v4(pp + 4, v4, v5, v6, v7);
            }
        }
        if (tid < TE_E && sDst[tid] >= 0) atomicAdd(&g_cnt[sDst[tid]], 1.0f);
        __syncthreads();
    }
}

// ---- out_kernel (unchanged) ----
__global__ __launch_bounds__(TPB) void out_kernel(
    const float* __restrict__ z, const float* __restrict__ S1,
    const float* __restrict__ Wu1, const float* __restrict__ bu1,
    const float* __restrict__ Wm2, const float* __restrict__ bm2,
    float* __restrict__ out, int N, int ntiles) {
    extern __shared__ float sm[];
    float* sWu1 = sm;
    float* sWm2 = sm + 8192;
    float* sbu1 = sm + 12288;
    float* sbm2 = sm + 12352;
    float* sZM = sm + 12416;

    const int tid = threadIdx.x;
    for (int i = tid; i < 8192; i += TPB) sWu1[i] = Wu1[i];
    for (int i = tid; i < 4096; i += TPB) sWm2[i] = Wm2[i];
    if (tid < 64) { sbu1[tid] = bu1[tid]; sbm2[tid] = bm2[tid]; }
    __syncthreads();

    const int wid = tid >> 5, lane = tid & 31;
    const int grp = wid >> 3;
    const int cb = (wid & 7) * 8;
    const int eb = grp * 128 + lane * 4;

    for (int tile = blockIdx.x; tile < ntiles; tile += gridDim.x) {
        const int base = tile * TE;
        for (int i = tid; i < 64 * TE; i += TPB) {
            int nl = i >> 6, k = i & 63;
            int gn = base + nl;
            float zv = 0.0f, sv = 0.0f;
            if (gn < N) {
                zv = z[(size_t)gn * 64 + k];
                sv = S1[(size_t)gn * 64 + k];
            }
            sZM[k * AP + nl] = zv;
            sZM[(64 + k) * AP + nl] = sv;
        }
        __syncthreads();

        ull acc[4][4];
        zero_acc(acc);
        gemmp(sZM + 64 * AP, AP, sWm2, 64, cb, eb, acc);

        float Mv[4][8];
#pragma unroll
        for (int e = 0; e < 4; ++e) {
            int gn = base + eb + e;
            float c = (gn < N) ? g_cnt[gn] : 0.0f;
            float rinv = 1.0f / fmaxf(c, 1.0f);
#pragma unroll
            for (int cp = 0; cp < 4; ++cp) {
                float lo, hi;
                unpack2(acc[cp][e], lo, hi);
                Mv[e][2 * cp] = (lo + c * sbm2[cb + 2 * cp]) * rinv;
                Mv[e][2 * cp + 1] = (hi + c * sbm2[cb + 2 * cp + 1]) * rinv;
            }
        }
        __syncthreads();

#pragma unroll
        for (int cp = 0; cp < 4; ++cp) {
            float4 v0 = make_float4(Mv[0][2 * cp], Mv[1][2 * cp],
                                    Mv[2][2 * cp], Mv[3][2 * cp]);
            float4 v1 = make_float4(Mv[0][2 * cp + 1], Mv[1][2 * cp + 1],
                                    Mv[2][2 * cp + 1], Mv[3][2 * cp + 1]);
            *reinterpret_cast<float4*>(sZM + (64 + cb + 2 * cp) * AP + eb) = v0;
            *reinterpret_cast<float4*>(sZM + (64 + cb + 2 * cp + 1) * AP + eb) = v1;
        }
        __syncthreads();

        zero_acc(acc);
        gemmp(sZM, AP, sWu1, 128, cb, eb, acc);
#pragma unroll
        for (int e = 0; e < 4; ++e) {
            int gn = base + eb + e;
            if (gn < N) {
                float v[8];
#pragma unroll
                for (int cp = 0; cp < 4; ++cp)
                    unpack2(acc[cp][e], v[2 * cp], v[2 * cp + 1]);
                float4 o0, o1;
                o0.x = fmaxf(v[0] + sbu1[cb + 0], 0.0f);
                o0.y = fmaxf(v[1] + sbu1[cb + 1], 0.0f);
                o0.z = fmaxf(v[2] + sbu1[cb + 2], 0.0f);
                o0.w = fmaxf(v[3] + sbu1[cb + 3], 0.0f);
                o1.x = fmaxf(v[4] + sbu1[cb + 4], 0.0f);
                o1.y = fmaxf(v[5] + sbu1[cb + 5], 0.0f);
                o1.z = fmaxf(v[6] + sbu1[cb + 6], 0.0f);
                o1.w = fmaxf(v[7] + sbu1[cb + 7], 0.0f);
                *reinterpret_cast<float4*>(&out[(size_t)gn * 64 + cb]) = o0;
                *reinterpret_cast<float4*>(&out[(size_t)gn * 64 + cb + 4]) = o1;
            }
        }
        __syncthreads();
    }
}

extern "C" void kernel_launch(void* const* d_in, const int* in_sizes, int n_in,
                              void* d_out, int out_size) {
    const float* z    = (const float*)d_in[0];
    const float* cent = (const float*)d_in[1];
    const void* ei    = d_in[2];
    const float* We1 = (const float*)d_in[3];
    const float* be1 = (const float*)d_in[4];
    const float* We2 = (const float*)d_in[5];
    const float* be2 = (const float*)d_in[6];
    const float* Wm1 = (const float*)d_in[7];
    const float* bm1 = (const float*)d_in[8];
    const float* Wm2 = (const float*)d_in[9];
    const float* bm2 = (const float*)d_in[10];
    const float* Wu1 = (const float*)d_in[11];
    const float* bu1 = (const float*)d_in[12];
    float* out = (float*)d_out;

    const int N = in_sizes[0] / 64;
    const int E = in_sizes[2] / 2;
    const int ntiles_e = (E + TE_E - 1) / TE_E;
    const int ntiles_n = (N + TE - 1) / TE;

    const size_t smem_edge = 18624 * sizeof(float);
    const size_t smem_pq   = 24832 * sizeof(float);
    const size_t smem_out  = 45696 * sizeof(float);

    cudaFuncSetAttribute(edge_kernel, cudaFuncAttributeMaxDynamicSharedMemorySize,
                         (int)smem_edge);
    cudaFuncSetAttribute(pq_kernel, cudaFuncAttributeMaxDynamicSharedMemorySize,
                         (int)smem_pq);
    cudaFuncSetAttribute(out_kernel, cudaFuncAttributeMaxDynamicSharedMemorySize,
                         (int)smem_out);

    detect_kernel<<<1, 32>>>((const unsigned long long*)ei);
    pq_kernel<<<ntiles_n, TPB, smem_pq>>>(z, Wm1, out, N, ntiles_n);
    edge_kernel<<<444, TPB_E, smem_edge>>>(cent, ei,
                                           We1, be1, We2, be2,
                                           Wm1, bm1,
                                           out, E, N, ntiles_e);
    out_kernel<<<ntiles_n, TPB, smem_out>>>(z, out, Wu1, bu1, Wm2, bm2,
                                            out, N, ntiles_n);
}